// round 5
// baseline (speedup 1.0000x reference)
#include <cuda_runtime.h>
#include <cuda_fp16.h>
#include <cstdint>

// ============================================================
// FullyFusedMLP 64 -> 128 -> 128 -> 128 -> 128 -> 64, ReLU on all but last.
// N = 1,048,576 rows fp32. sm_103 plain-target version (no tcgen05):
// mma.sync.m16n8k16 fp16 with Ootomo hi/lo 3-pass split, fp32 accum.
// Activations stay in registers between layers (C-frag == next A-frag).
// Weights: prep kernel builds swizzled fp16 hi/lo image; main kernel
// double-buffers per-layer weights into SMEM with cp.async.
// ============================================================

#define THREADS 256

// Weight image: per layer [hi block | lo block], XOR-swizzled rows.
// l0: W_in[128,64]  rb=128B  hi 16KB   @ 0
// l1-3: W_hid[128,128] rb=256B hi 32KB @ 32768,98304,163840
// l4: W_out[64,128] rb=256B  hi 16KB   @ 229376          total 256KB
__device__ __align__(256) unsigned char g_w[262144];

#define SM_BIAS 0           // 576 floats
#define SM_BUF0 4096        // 64KB weight buffer A
#define SM_BUF1 69632       // 64KB weight buffer B
#define SM_TOTAL 135168

static __device__ __forceinline__ uint32_t smem_u32(const void* p) {
    uint32_t a;
    asm("{ .reg .u64 t; cvta.to.shared.u64 t, %1; cvt.u32.u64 %0, t; }"
        : "=r"(a) : "l"(p));
    return a;
}

#define CP16(dst, src) \
    asm volatile("cp.async.cg.shared.global [%0], [%1], 16;\n" \
                 :: "r"(dst), "l"(src))
#define CPCOMMIT() asm volatile("cp.async.commit_group;\n" ::: "memory")
#define CPWAIT0()  asm volatile("cp.async.wait_group 0;\n" ::: "memory")

static __device__ __forceinline__ void ldsm_x2(uint32_t& r0, uint32_t& r1, uint32_t addr) {
    asm volatile("ldmatrix.sync.aligned.m8n8.x2.shared.b16 {%0,%1}, [%2];\n"
                 : "=r"(r0), "=r"(r1) : "r"(addr));
}

static __device__ __forceinline__ void mma16816(float acc[4], const uint32_t a[4],
                                                const uint32_t b[2]) {
    asm volatile(
        "mma.sync.aligned.m16n8k16.row.col.f32.f16.f16.f32 "
        "{%0,%1,%2,%3}, {%4,%5,%6,%7}, {%8,%9}, {%0,%1,%2,%3};\n"
        : "+f"(acc[0]), "+f"(acc[1]), "+f"(acc[2]), "+f"(acc[3])
        : "r"(a[0]), "r"(a[1]), "r"(a[2]), "r"(a[3]), "r"(b[0]), "r"(b[1]));
}

static __device__ __forceinline__ uint32_t packh2(float a, float b) {
    __half2 h = __floats2half2_rn(a, b);
    return *reinterpret_cast<uint32_t*>(&h);
}
static __device__ __forceinline__ float resid(float a) {
    return a - __half2float(__float2half_rn(a));
}

// swizzled byte offset of W[n][k] within a weight block (rb = row bytes)
static __device__ __forceinline__ int wsw(int n, int k, int rb) {
    return n * rb + ((((k >> 3) ^ (n & 7))) << 4) + ((k & 7) << 1);
}

// ============================================================
// Prep: fp32 weights -> fp16 hi/lo swizzled image (one thread/element)
// ============================================================
__global__ void prep_weights(const float* __restrict__ w_in,
                             const float* __restrict__ w_hid,
                             const float* __restrict__ w_out) {
    int idx = blockIdx.x * blockDim.x + threadIdx.x;
    if (idx >= 65536) return;
    int l, n, k;
    float v;
    if (idx < 8192)       { l = 0; n = idx >> 6; k = idx & 63; v = w_in[idx]; }
    else if (idx < 57344) { int r = idx - 8192; l = 1 + (r >> 14);
                            n = (r >> 7) & 127; k = r & 127; v = w_hid[r]; }
    else                  { int r = idx - 57344; l = 4;
                            n = r >> 7; k = r & 127; v = w_out[r]; }
    const int woff[5] = {0, 32768, 98304, 163840, 229376};
    const int rb[5]   = {128, 256, 256, 256, 256};
    const int hs[5]   = {16384, 32768, 32768, 32768, 16384};
    __half hi = __float2half_rn(v);
    __half lo = __float2half_rn(v - __half2float(hi));
    int off = woff[l] + wsw(n, k, rb[l]);
    *(__half*)(g_w + off)         = hi;
    *(__half*)(g_w + off + hs[l]) = lo;
}

// ============================================================
// One layer of MMAs: acc[N/8][4] = split-fp16( A ) * split-fp16( W^T )
// Two n8 columns processed together for 2 independent accumulation chains.
// ============================================================
template <int NKC, int NNC, int RB>
static __device__ __forceinline__ void run_layer(uint32_t wsm, int hisize, int lane,
                                                 const uint32_t Ahi[8][4],
                                                 const uint32_t Alo[8][4],
                                                 float acc[16][4]) {
    const int t  = lane & 15;
    const int nl = t & 7;    // row within 8-row ldmatrix group
    const int h8 = t >> 3;   // which 8-half k-chunk this lane fetches
#pragma unroll
    for (int np = 0; np < NNC / 2; ++np) {
        float* a0 = acc[2 * np];
        float* a1 = acc[2 * np + 1];
#pragma unroll
        for (int r = 0; r < 4; ++r) { a0[r] = 0.f; a1[r] = 0.f; }
        uint32_t B0[NKC][2], B1[NKC][2];
        uint32_t base0 = wsm + (uint32_t)((16 * np + nl) * RB);
        uint32_t base1 = base0 + 8 * RB;
#pragma unroll
        for (int j = 0; j < NKC; ++j) {
            uint32_t sw = (uint32_t)(((2 * j + h8) ^ nl) << 4);
            ldsm_x2(B0[j][0], B0[j][1], base0 + sw);
            ldsm_x2(B1[j][0], B1[j][1], base1 + sw);
        }
#pragma unroll
        for (int j = 0; j < NKC; ++j) {   // pass 1: Ahi * Whi
            mma16816(a0, Ahi[j], B0[j]);
            mma16816(a1, Ahi[j], B1[j]);
        }
#pragma unroll
        for (int j = 0; j < NKC; ++j) {   // pass 2: Alo * Whi
            mma16816(a0, Alo[j], B0[j]);
            mma16816(a1, Alo[j], B1[j]);
        }
#pragma unroll
        for (int j = 0; j < NKC; ++j) {   // reload lo weights
            uint32_t sw = (uint32_t)(((2 * j + h8) ^ nl) << 4);
            ldsm_x2(B0[j][0], B0[j][1], base0 + (uint32_t)hisize + sw);
            ldsm_x2(B1[j][0], B1[j][1], base1 + (uint32_t)hisize + sw);
        }
#pragma unroll
        for (int j = 0; j < NKC; ++j) {   // pass 3: Ahi * Wlo
            mma16816(a0, Ahi[j], B0[j]);
            mma16816(a1, Ahi[j], B1[j]);
        }
    }
}

// bias + ReLU + hi/lo split; C-frag pairs become next-layer A-frags in place.
template <int NNC>
static __device__ __forceinline__ void epi_relu(const float acc[16][4], const float* bsm,
                                                int q, uint32_t Ahi[8][4],
                                                uint32_t Alo[8][4]) {
#pragma unroll
    for (int tc = 0; tc < NNC / 2; ++tc) {
#pragma unroll
        for (int h = 0; h < 2; ++h) {
            const float* a = acc[2 * tc + h];
            float2 b = *(const float2*)(bsm + (2 * tc + h) * 8 + 2 * q);
            float v0 = fmaxf(a[0] + b.x, 0.f), v1 = fmaxf(a[1] + b.y, 0.f);
            float v2 = fmaxf(a[2] + b.x, 0.f), v3 = fmaxf(a[3] + b.y, 0.f);
            Ahi[tc][2 * h + 0] = packh2(v0, v1);
            Ahi[tc][2 * h + 1] = packh2(v2, v3);
            Alo[tc][2 * h + 0] = packh2(resid(v0), resid(v1));
            Alo[tc][2 * h + 1] = packh2(resid(v2), resid(v3));
        }
    }
}

static __device__ __forceinline__ void copy_w(uint32_t dst, int gofs, int n16, int tid) {
    unsigned long long src =
        (unsigned long long)__cvta_generic_to_global(g_w + gofs);
    for (int i = tid; i < n16; i += THREADS)
        CP16(dst + (uint32_t)(i * 16), src + (unsigned long long)i * 16);
}

// ============================================================
// Main kernel: 1 CTA = 128 rows, 8 warps x 16 rows.
// ============================================================
__global__ void __launch_bounds__(THREADS, 1)
mlp_kernel(const float* __restrict__ x, const float* __restrict__ b_in,
           const float* __restrict__ b_hid, const float* __restrict__ b_out,
           float* __restrict__ out) {
    extern __shared__ char smem[];
    const uint32_t sb = smem_u32(smem);
    const int tid = threadIdx.x, wid = tid >> 5, lane = tid & 31;
    const int q = lane & 3, r0 = lane >> 2;
    float* bias = (float*)(smem + SM_BIAS);

    if (tid < 128) bias[tid] = b_in[tid];
    for (int i = tid; i < 384; i += THREADS) bias[128 + i] = b_hid[i];
    if (tid < 64) bias[512 + tid] = b_out[tid];

    // start layer-0 weight copy (32KB) immediately
    copy_w(sb + SM_BUF0, 0, 2048, tid);
    CPCOMMIT();

    // ---- load input tile as fp16 hi/lo A-fragments (K=64 -> 4 chunks) ----
    uint32_t Ahi[8][4], Alo[8][4];
    {
        const float* xr = x + ((size_t)blockIdx.x * 128 + wid * 16) * 64 + 2 * q;
#pragma unroll
        for (int j = 0; j < 4; ++j)
#pragma unroll
            for (int p = 0; p < 4; ++p) {
                int dr = (p & 1) * 8, dk = (p >> 1) * 8;
                float2 v = *(const float2*)(xr + (r0 + dr) * 64 + j * 16 + dk);
                Ahi[j][p] = packh2(v.x, v.y);
                Alo[j][p] = packh2(resid(v.x), resid(v.y));
            }
    }
    CPWAIT0();
    __syncthreads();

    float acc[16][4];

    // L0: K=64, N=128, weights in BUF0; prefetch L1 into BUF1
    copy_w(sb + SM_BUF1, 32768, 4096, tid); CPCOMMIT();
    run_layer<4, 16, 128>(sb + SM_BUF0, 16384, lane, Ahi, Alo, acc);
    epi_relu<16>(acc, bias + 0, q, Ahi, Alo);
    CPWAIT0(); __syncthreads();

    // L1: BUF1; prefetch L2 into BUF0
    copy_w(sb + SM_BUF0, 98304, 4096, tid); CPCOMMIT();
    run_layer<8, 16, 256>(sb + SM_BUF1, 32768, lane, Ahi, Alo, acc);
    epi_relu<16>(acc, bias + 128, q, Ahi, Alo);
    CPWAIT0(); __syncthreads();

    // L2: BUF0; prefetch L3 into BUF1
    copy_w(sb + SM_BUF1, 163840, 4096, tid); CPCOMMIT();
    run_layer<8, 16, 256>(sb + SM_BUF0, 32768, lane, Ahi, Alo, acc);
    epi_relu<16>(acc, bias + 256, q, Ahi, Alo);
    CPWAIT0(); __syncthreads();

    // L3: BUF1; prefetch L4 (32KB) into BUF0
    copy_w(sb + SM_BUF0, 229376, 2048, tid); CPCOMMIT();
    run_layer<8, 16, 256>(sb + SM_BUF1, 32768, lane, Ahi, Alo, acc);
    epi_relu<16>(acc, bias + 384, q, Ahi, Alo);
    CPWAIT0(); __syncthreads();

    // L4: K=128, N=64, no ReLU; add b_out and store fp32
    run_layer<8, 8, 256>(sb + SM_BUF0, 16384, lane, Ahi, Alo, acc);
    {
        float* orow = out + ((size_t)blockIdx.x * 128 + wid * 16) * 64 + 2 * q;
#pragma unroll
        for (int nc = 0; nc < 8; ++nc) {
            float2 b = *(const float2*)(bias + 512 + nc * 8 + 2 * q);
            float2 v0 = make_float2(acc[nc][0] + b.x, acc[nc][1] + b.y);
            float2 v1 = make_float2(acc[nc][2] + b.x, acc[nc][3] + b.y);
            *(float2*)(orow + r0 * 64 + nc * 8)       = v0;
            *(float2*)(orow + (r0 + 8) * 64 + nc * 8) = v1;
        }
    }
}

extern "C" void kernel_launch(void* const* d_in, const int* in_sizes, int n_in,
                              void* d_out, int out_size) {
    const float* x     = (const float*)d_in[0];
    const float* w_in  = (const float*)d_in[1];
    const float* b_in  = (const float*)d_in[2];
    const float* w_hid = (const float*)d_in[3];
    const float* b_hid = (const float*)d_in[4];
    const float* w_out = (const float*)d_in[5];
    const float* b_out = (const float*)d_in[6];
    float* out = (float*)d_out;

    int n_rows = in_sizes[0] / 64;
    int grid = n_rows / 128;   // 8192

    cudaFuncSetAttribute(mlp_kernel, cudaFuncAttributeMaxDynamicSharedMemorySize,
                         SM_TOTAL);

    prep_weights<<<256, 256>>>(w_in, w_hid, w_out);
    mlp_kernel<<<grid, THREADS, SM_TOTAL>>>(x, b_in, b_hid, b_out, out);
}

// round 7
// speedup vs baseline: 1.3626x; 1.3626x over previous
#include <cuda_runtime.h>
#include <cuda_fp16.h>
#include <cstdint>

// ============================================================
// FullyFusedMLP 64 -> 128 -> 128 -> 128 -> 128 -> 64, ReLU on all but last.
// N = 1,048,576 rows fp32.  mma.sync.m16n8k16 fp16, fp32 accum.
// 2-pass split: (Ahi + Alo) x Whi  — activation residual kept, weight
// residual dropped (error budget: ~6e-4 < 1e-3 gate).
// Activations stay in registers across all 5 layers (C-frag == next A-frag).
// 4-column MMA groups -> 4 independent accumulation chains per warp.
// ============================================================

#define THREADS 256

// Weight image (hi fp16 only), XOR-swizzled rows:
// l0: W_in [128,64]  rb=128B 16KB @ 0
// l1-3: W_hid[128,128] rb=256B 32KB @ 16384 / 49152 / 81920
// l4: W_out[64,128]  rb=256B 16KB @ 114688      total 128KB
__device__ __align__(256) unsigned char g_w[131072];

#define SM_BIAS 0           // 576 floats
#define SM_BUF0 4096        // 32KB weight buffer A
#define SM_BUF1 36864       // 32KB weight buffer B
#define SM_TOTAL 69632

static __device__ __forceinline__ uint32_t smem_u32(const void* p) {
    uint32_t a;
    asm("{ .reg .u64 t; cvta.to.shared.u64 t, %1; cvt.u32.u64 %0, t; }"
        : "=r"(a) : "l"(p));
    return a;
}

#define CP16(dst, src) \
    asm volatile("cp.async.cg.shared.global [%0], [%1], 16;\n" \
                 :: "r"(dst), "l"(src))
#define CPCOMMIT() asm volatile("cp.async.commit_group;\n" ::: "memory")
#define CPWAIT0()  asm volatile("cp.async.wait_group 0;\n" ::: "memory")

static __device__ __forceinline__ void ldsm_x2(uint32_t& r0, uint32_t& r1, uint32_t addr) {
    asm volatile("ldmatrix.sync.aligned.m8n8.x2.shared.b16 {%0,%1}, [%2];\n"
                 : "=r"(r0), "=r"(r1) : "r"(addr));
}

static __device__ __forceinline__ void mma16816(float acc[4], const uint32_t a[4],
                                                const uint32_t b[2]) {
    asm volatile(
        "mma.sync.aligned.m16n8k16.row.col.f32.f16.f16.f32 "
        "{%0,%1,%2,%3}, {%4,%5,%6,%7}, {%8,%9}, {%0,%1,%2,%3};\n"
        : "+f"(acc[0]), "+f"(acc[1]), "+f"(acc[2]), "+f"(acc[3])
        : "r"(a[0]), "r"(a[1]), "r"(a[2]), "r"(a[3]), "r"(b[0]), "r"(b[1]));
}

static __device__ __forceinline__ uint32_t packh2(float a, float b) {
    __half2 h = __floats2half2_rn(a, b);
    return *reinterpret_cast<uint32_t*>(&h);
}
static __device__ __forceinline__ float resid(float a) {
    return a - __half2float(__float2half_rn(a));
}

// swizzled byte offset of W[n][k] within a weight block (rb = row bytes)
static __device__ __forceinline__ int wsw(int n, int k, int rb) {
    return n * rb + ((((k >> 3) ^ (n & 7))) << 4) + ((k & 7) << 1);
}

// ============================================================
// Prep: fp32 weights -> fp16 hi swizzled image
// ============================================================
__global__ void prep_weights(const float* __restrict__ w_in,
                             const float* __restrict__ w_hid,
                             const float* __restrict__ w_out) {
    int idx = blockIdx.x * blockDim.x + threadIdx.x;
    if (idx >= 65536) return;
    int l, n, k;
    float v;
    if (idx < 8192)       { l = 0; n = idx >> 6; k = idx & 63; v = w_in[idx]; }
    else if (idx < 57344) { int r = idx - 8192; l = 1 + (r >> 14);
                            n = (r >> 7) & 127; k = r & 127; v = w_hid[r]; }
    else                  { int r = idx - 57344; l = 4;
                            n = r >> 7; k = r & 127; v = w_out[r]; }
    const int woff[5] = {0, 16384, 49152, 81920, 114688};
    const int rb[5]   = {128, 256, 256, 256, 256};
    int off = woff[l] + wsw(n, k, rb[l]);
    *(__half*)(g_w + off) = __float2half_rn(v);
}

// ============================================================
// One layer: acc[NNC][4] = (Ahi + Alo) * Whi^T,  4-column groups.
// ============================================================
template <int NKC, int NNC, int RB>
static __device__ __forceinline__ void run_layer(uint32_t wsm, int lane,
                                                 const uint32_t Ahi[8][4],
                                                 const uint32_t Alo[8][4],
                                                 float acc[16][4]) {
    const int t  = lane & 15;
    const int nl = t & 7;    // row within 8-row ldmatrix group
    const int h8 = t >> 3;   // which k-half this lane fetches
#pragma unroll
    for (int g = 0; g < NNC / 4; ++g) {
        uint32_t B[4][NKC][2];
#pragma unroll
        for (int c = 0; c < 4; ++c) {
            uint32_t base = wsm + (uint32_t)((32 * g + 8 * c + nl) * RB);
#pragma unroll
            for (int j = 0; j < NKC; ++j) {
                uint32_t sw = (uint32_t)(((2 * j + h8) ^ nl) << 4);
                ldsm_x2(B[c][j][0], B[c][j][1], base + sw);
            }
        }
#pragma unroll
        for (int c = 0; c < 4; ++c)
#pragma unroll
            for (int r = 0; r < 4; ++r) acc[4 * g + c][r] = 0.f;
        // pass 1: Ahi * Whi  (4 independent chains, reuse distance 4)
#pragma unroll
        for (int j = 0; j < NKC; ++j)
#pragma unroll
            for (int c = 0; c < 4; ++c)
                mma16816(acc[4 * g + c], Ahi[j], B[c][j]);
        // pass 2: Alo * Whi
#pragma unroll
        for (int j = 0; j < NKC; ++j)
#pragma unroll
            for (int c = 0; c < 4; ++c)
                mma16816(acc[4 * g + c], Alo[j], B[c][j]);
    }
}

// bias + ReLU + hi/lo split; C-frag pairs become next-layer A-frags in place.
template <int NNC>
static __device__ __forceinline__ void epi_relu(const float acc[16][4], const float* bsm,
                                                int q, uint32_t Ahi[8][4],
                                                uint32_t Alo[8][4]) {
#pragma unroll
    for (int tc = 0; tc < NNC / 2; ++tc) {
#pragma unroll
        for (int h = 0; h < 2; ++h) {
            const float* a = acc[2 * tc + h];
            float2 b = *(const float2*)(bsm + (2 * tc + h) * 8 + 2 * q);
            float v0 = fmaxf(a[0] + b.x, 0.f), v1 = fmaxf(a[1] + b.y, 0.f);
            float v2 = fmaxf(a[2] + b.x, 0.f), v3 = fmaxf(a[3] + b.y, 0.f);
            Ahi[tc][2 * h + 0] = packh2(v0, v1);
            Ahi[tc][2 * h + 1] = packh2(v2, v3);
            Alo[tc][2 * h + 0] = packh2(resid(v0), resid(v1));
            Alo[tc][2 * h + 1] = packh2(resid(v2), resid(v3));
        }
    }
}

static __device__ __forceinline__ void copy_w(uint32_t dst, int gofs, int n16, int tid) {
    unsigned long long src =
        (unsigned long long)__cvta_generic_to_global(g_w + gofs);
    for (int i = tid; i < n16; i += THREADS)
        CP16(dst + (uint32_t)(i * 16), src + (unsigned long long)i * 16);
}

// ============================================================
// Main kernel: 1 CTA = 128 rows, 8 warps x 16 rows.
// ============================================================
__global__ void __launch_bounds__(THREADS, 1)
mlp_kernel(const float* __restrict__ x, const float* __restrict__ b_in,
           const float* __restrict__ b_hid, const float* __restrict__ b_out,
           float* __restrict__ out) {
    extern __shared__ char smem[];
    const uint32_t sb = smem_u32(smem);
    const int tid = threadIdx.x, wid = tid >> 5, lane = tid & 31;
    const int q = lane & 3, r0 = lane >> 2;
    float* bias = (float*)(smem + SM_BIAS);

    if (tid < 128) bias[tid] = b_in[tid];
    for (int i = tid; i < 384; i += THREADS) bias[128 + i] = b_hid[i];
    if (tid < 64) bias[512 + tid] = b_out[tid];

    // start layer-0 weight copy (16KB) immediately
    copy_w(sb + SM_BUF0, 0, 1024, tid);
    CPCOMMIT();

    // ---- load input tile as fp16 hi/lo A-fragments (K=64 -> 4 chunks) ----
    uint32_t Ahi[8][4], Alo[8][4];
    {
        const float* xr = x + ((size_t)blockIdx.x * 128 + wid * 16) * 64 + 2 * q;
#pragma unroll
        for (int j = 0; j < 4; ++j)
#pragma unroll
            for (int p = 0; p < 4; ++p) {
                int dr = (p & 1) * 8, dk = (p >> 1) * 8;
                float2 v = *(const float2*)(xr + (r0 + dr) * 64 + j * 16 + dk);
                Ahi[j][p] = packh2(v.x, v.y);
                Alo[j][p] = packh2(resid(v.x), resid(v.y));
            }
    }
    CPWAIT0();
    __syncthreads();

    float acc[16][4];

    // L0: K=64, N=128, weights in BUF0; prefetch L1 into BUF1
    copy_w(sb + SM_BUF1, 16384, 2048, tid); CPCOMMIT();
    run_layer<4, 16, 128>(sb + SM_BUF0, lane, Ahi, Alo, acc);
    epi_relu<16>(acc, bias + 0, q, Ahi, Alo);
    CPWAIT0(); __syncthreads();

    // L1: BUF1; prefetch L2 into BUF0
    copy_w(sb + SM_BUF0, 49152, 2048, tid); CPCOMMIT();
    run_layer<8, 16, 256>(sb + SM_BUF1, lane, Ahi, Alo, acc);
    epi_relu<16>(acc, bias + 128, q, Ahi, Alo);
    CPWAIT0(); __syncthreads();

    // L2: BUF0; prefetch L3 into BUF1
    copy_w(sb + SM_BUF1, 81920, 2048, tid); CPCOMMIT();
    run_layer<8, 16, 256>(sb + SM_BUF0, lane, Ahi, Alo, acc);
    epi_relu<16>(acc, bias + 256, q, Ahi, Alo);
    CPWAIT0(); __syncthreads();

    // L3: BUF1; prefetch L4 (16KB) into BUF0
    copy_w(sb + SM_BUF0, 114688, 1024, tid); CPCOMMIT();
    run_layer<8, 16, 256>(sb + SM_BUF1, lane, Ahi, Alo, acc);
    epi_relu<16>(acc, bias + 384, q, Ahi, Alo);
    CPWAIT0(); __syncthreads();

    // L4: K=128, N=64, no ReLU; add b_out and store fp32
    run_layer<8, 8, 256>(sb + SM_BUF0, lane, Ahi, Alo, acc);
    {
        float* orow = out + ((size_t)blockIdx.x * 128 + wid * 16) * 64 + 2 * q;
#pragma unroll
        for (int nc = 0; nc < 8; ++nc) {
            float2 b = *(const float2*)(bias + 512 + nc * 8 + 2 * q);
            float2 v0 = make_float2(acc[nc][0] + b.x, acc[nc][1] + b.y);
            float2 v1 = make_float2(acc[nc][2] + b.x, acc[nc][3] + b.y);
            *(float2*)(orow + r0 * 64 + nc * 8)       = v0;
            *(float2*)(orow + (r0 + 8) * 64 + nc * 8) = v1;
        }
    }
}

extern "C" void kernel_launch(void* const* d_in, const int* in_sizes, int n_in,
                              void* d_out, int out_size) {
    const float* x     = (const float*)d_in[0];
    const float* w_in  = (const float*)d_in[1];
    const float* b_in  = (const float*)d_in[2];
    const float* w_hid = (const float*)d_in[3];
    const float* b_hid = (const float*)d_in[4];
    const float* w_out = (const float*)d_in[5];
    const float* b_out = (const float*)d_in[6];
    float* out = (float*)d_out;

    int n_rows = in_sizes[0] / 64;
    int grid = n_rows / 128;   // 8192

    cudaFuncSetAttribute(mlp_kernel, cudaFuncAttributeMaxDynamicSharedMemorySize,
                         SM_TOTAL);

    prep_weights<<<256, 256>>>(w_in, w_hid, w_out);
    mlp_kernel<<<grid, THREADS, SM_TOTAL>>>(x, b_in, b_hid, b_out, out);
}

// round 10
// speedup vs baseline: 1.4389x; 1.0560x over previous
#include <cuda_runtime.h>
#include <cuda_fp16.h>
#include <cstdint>

// ============================================================
// FullyFusedMLP 64 -> 128 -> 128 -> 128 -> 128 -> 64, ReLU on all but last.
// N = 1,048,576 rows fp32.  mma.sync.m16n8k16 fp16, fp32 accum.
// 2-pass split: (Ahi + Alo) x Whi.  Activations stay in registers across
// all 5 layers.  j-major fused loop: ldmatrix.x4 (2 columns/op) prefetches
// the next k-step's B fragments while 8 MMAs consume the current ones.
// ============================================================

#define THREADS 256

// Weight image (hi fp16 only), XOR-swizzled rows:
// l0: W_in [128,64]  rb=128B 16KB @ 0
// l1-3: W_hid[128,128] rb=256B 32KB @ 16384 / 49152 / 81920
// l4: W_out[64,128]  rb=256B 16KB @ 114688      total 128KB
__device__ __align__(256) unsigned char g_w[131072];

#define SM_BIAS 0           // 576 floats
#define SM_BUF0 4096        // 32KB weight buffer A
#define SM_BUF1 36864       // 32KB weight buffer B
#define SM_TOTAL 69632

static __device__ __forceinline__ uint32_t smem_u32(const void* p) {
    uint32_t a;
    asm("{ .reg .u64 t; cvta.to.shared.u64 t, %1; cvt.u32.u64 %0, t; }"
        : "=r"(a) : "l"(p));
    return a;
}

#define CP16(dst, src) \
    asm volatile("cp.async.cg.shared.global [%0], [%1], 16;\n" \
                 :: "r"(dst), "l"(src))
#define CPCOMMIT() asm volatile("cp.async.commit_group;\n" ::: "memory")
#define CPWAIT0()  asm volatile("cp.async.wait_group 0;\n" ::: "memory")

static __device__ __forceinline__ void ldsm_x4(uint32_t& r0, uint32_t& r1,
                                               uint32_t& r2, uint32_t& r3,
                                               uint32_t addr) {
    asm volatile("ldmatrix.sync.aligned.m8n8.x4.shared.b16 {%0,%1,%2,%3}, [%4];\n"
                 : "=r"(r0), "=r"(r1), "=r"(r2), "=r"(r3) : "r"(addr));
}

static __device__ __forceinline__ void mma16816(float acc[4], const uint32_t a[4],
                                                const uint32_t b[2]) {
    asm volatile(
        "mma.sync.aligned.m16n8k16.row.col.f32.f16.f16.f32 "
        "{%0,%1,%2,%3}, {%4,%5,%6,%7}, {%8,%9}, {%0,%1,%2,%3};\n"
        : "+f"(acc[0]), "+f"(acc[1]), "+f"(acc[2]), "+f"(acc[3])
        : "r"(a[0]), "r"(a[1]), "r"(a[2]), "r"(a[3]), "r"(b[0]), "r"(b[1]));
}

static __device__ __forceinline__ uint32_t packh2(float a, float b) {
    __half2 h = __floats2half2_rn(a, b);
    return *reinterpret_cast<uint32_t*>(&h);
}
static __device__ __forceinline__ float resid(float a) {
    return a - __half2float(__float2half_rn(a));
}

// swizzled byte offset of W[n][k] within a weight block (rb = row bytes)
static __device__ __forceinline__ int wsw(int n, int k, int rb) {
    return n * rb + ((((k >> 3) ^ (n & 7))) << 4) + ((k & 7) << 1);
}

// ============================================================
// Prep: fp32 weights -> fp16 hi swizzled image
// ============================================================
__global__ void prep_weights(const float* __restrict__ w_in,
                             const float* __restrict__ w_hid,
                             const float* __restrict__ w_out) {
    int idx = blockIdx.x * blockDim.x + threadIdx.x;
    if (idx >= 65536) return;
    int l, n, k;
    float v;
    if (idx < 8192)       { l = 0; n = idx >> 6; k = idx & 63; v = w_in[idx]; }
    else if (idx < 57344) { int r = idx - 8192; l = 1 + (r >> 14);
                            n = (r >> 7) & 127; k = r & 127; v = w_hid[r]; }
    else                  { int r = idx - 57344; l = 4;
                            n = r >> 7; k = r & 127; v = w_out[r]; }
    const int woff[5] = {0, 16384, 49152, 81920, 114688};
    const int rb[5]   = {128, 256, 256, 256, 256};
    int off = woff[l] + wsw(n, k, rb[l]);
    *(__half*)(g_w + off) = __float2half_rn(v);
}

// ============================================================
// One layer: acc[NNC][4] = (Ahi + Alo) * Whi^T.
// 4-column groups, j-major, double-buffered ldmatrix.x4 prefetch.
// Lane mapping for x4: nl = lane&7 (row in 8-group), h8 = (lane>>3)&1
// (k-half), cp = lane>>4 (column within pair). One x4 = 2 n8-columns.
// ============================================================
template <int NKC, int NNC, int RB>
static __device__ __forceinline__ void run_layer(uint32_t wsm, int lane,
                                                 const uint32_t Ahi[8][4],
                                                 const uint32_t Alo[8][4],
                                                 float acc[16][4]) {
    const int nl = lane & 7;
    const int h8 = (lane >> 3) & 1;
    const int cp = lane >> 4;
#pragma unroll
    for (int g = 0; g < NNC / 4; ++g) {
#pragma unroll
        for (int c = 0; c < 4; ++c)
#pragma unroll
            for (int r = 0; r < 4; ++r) acc[4 * g + c][r] = 0.f;

        uint32_t B[2][8];   // [buffer][2 col-pairs x 2 cols x 2 regs]
        const uint32_t base = wsm + (uint32_t)((32 * g + 8 * cp + nl) * RB);
        {
            uint32_t sw = (uint32_t)((h8 ^ nl) << 4);
            ldsm_x4(B[0][0], B[0][1], B[0][2], B[0][3], base + sw);
            ldsm_x4(B[0][4], B[0][5], B[0][6], B[0][7], base + 16 * RB + sw);
        }
#pragma unroll
        for (int j = 0; j < NKC; ++j) {
            const int cb = j & 1, nb = cb ^ 1;
            if (j + 1 < NKC) {
                uint32_t sw = (uint32_t)(((2 * (j + 1) + h8) ^ nl) << 4);
                ldsm_x4(B[nb][0], B[nb][1], B[nb][2], B[nb][3], base + sw);
                ldsm_x4(B[nb][4], B[nb][5], B[nb][6], B[nb][7], base + 16 * RB + sw);
            }
            mma16816(acc[4 * g + 0], Ahi[j], &B[cb][0]);
            mma16816(acc[4 * g + 1], Ahi[j], &B[cb][2]);
            mma16816(acc[4 * g + 2], Ahi[j], &B[cb][4]);
            mma16816(acc[4 * g + 3], Ahi[j], &B[cb][6]);
            mma16816(acc[4 * g + 0], Alo[j], &B[cb][0]);
            mma16816(acc[4 * g + 1], Alo[j], &B[cb][2]);
            mma16816(acc[4 * g + 2], Alo[j], &B[cb][4]);
            mma16816(acc[4 * g + 3], Alo[j], &B[cb][6]);
        }
    }
}

// bias + ReLU + hi/lo split; C-frag pairs become next-layer A-frags in place.
template <int NNC>
static __device__ __forceinline__ void epi_relu(const float acc[16][4], const float* bsm,
                                                int q, uint32_t Ahi[8][4],
                                                uint32_t Alo[8][4]) {
#pragma unroll
    for (int tc = 0; tc < NNC / 2; ++tc) {
#pragma unroll
        for (int h = 0; h < 2; ++h) {
            const float* a = acc[2 * tc + h];
            float2 b = *(const float2*)(bsm + (2 * tc + h) * 8 + 2 * q);
            float v0 = fmaxf(a[0] + b.x, 0.f), v1 = fmaxf(a[1] + b.y, 0.f);
            float v2 = fmaxf(a[2] + b.x, 0.f), v3 = fmaxf(a[3] + b.y, 0.f);
            Ahi[tc][2 * h + 0] = packh2(v0, v1);
            Ahi[tc][2 * h + 1] = packh2(v2, v3);
            Alo[tc][2 * h + 0] = packh2(resid(v0), resid(v1));
            Alo[tc][2 * h + 1] = packh2(resid(v2), resid(v3));
        }
    }
}

static __device__ __forceinline__ void copy_w(uint32_t dst, int gofs, int n16, int tid) {
    unsigned long long src =
        (unsigned long long)__cvta_generic_to_global(g_w + gofs);
    for (int i = tid; i < n16; i += THREADS)
        CP16(dst + (uint32_t)(i * 16), src + (unsigned long long)i * 16);
}

// ============================================================
// Main kernel: 1 CTA = 128 rows, 8 warps x 16 rows.
// ============================================================
__global__ void __launch_bounds__(THREADS, 1)
mlp_kernel(const float* __restrict__ x, const float* __restrict__ b_in,
           const float* __restrict__ b_hid, const float* __restrict__ b_out,
           float* __restrict__ out) {
    extern __shared__ char smem[];
    const uint32_t sb = smem_u32(smem);
    const int tid = threadIdx.x, wid = tid >> 5, lane = tid & 31;
    const int q = lane & 3, r0 = lane >> 2;
    float* bias = (float*)(smem + SM_BIAS);

    if (tid < 128) bias[tid] = b_in[tid];
    for (int i = tid; i < 384; i += THREADS) bias[128 + i] = b_hid[i];
    if (tid < 64) bias[512 + tid] = b_out[tid];

    // start layer-0 weight copy (16KB) immediately
    copy_w(sb + SM_BUF0, 0, 1024, tid);
    CPCOMMIT();

    // ---- load input tile as fp16 hi/lo A-fragments (K=64 -> 4 chunks) ----
    uint32_t Ahi[8][4], Alo[8][4];
    {
        const float* xr = x + ((size_t)blockIdx.x * 128 + wid * 16) * 64 + 2 * q;
#pragma unroll
        for (int j = 0; j < 4; ++j)
#pragma unroll
            for (int p = 0; p < 4; ++p) {
                int dr = (p & 1) * 8, dk = (p >> 1) * 8;
                float2 v = *(const float2*)(xr + (r0 + dr) * 64 + j * 16 + dk);
                Ahi[j][p] = packh2(v.x, v.y);
                Alo[j][p] = packh2(resid(v.x), resid(v.y));
            }
    }
    CPWAIT0();
    __syncthreads();

    float acc[16][4];

    // L0: K=64, N=128, weights in BUF0; prefetch L1 into BUF1
    copy_w(sb + SM_BUF1, 16384, 2048, tid); CPCOMMIT();
    run_layer<4, 16, 128>(sb + SM_BUF0, lane, Ahi, Alo, acc);
    epi_relu<16>(acc, bias + 0, q, Ahi, Alo);
    CPWAIT0(); __syncthreads();

    // L1: BUF1; prefetch L2 into BUF0
    copy_w(sb + SM_BUF0, 49152, 2048, tid); CPCOMMIT();
    run_layer<8, 16, 256>(sb + SM_BUF1, lane, Ahi, Alo, acc);
    epi_relu<16>(acc, bias + 128, q, Ahi, Alo);
    CPWAIT0(); __syncthreads();

    // L2: BUF0; prefetch L3 into BUF1
    copy_w(sb + SM_BUF1, 81920, 2048, tid); CPCOMMIT();
    run_layer<8, 16, 256>(sb + SM_BUF0, lane, Ahi, Alo, acc);
    epi_relu<16>(acc, bias + 256, q, Ahi, Alo);
    CPWAIT0(); __syncthreads();

    // L3: BUF1; prefetch L4 (16KB) into BUF0
    copy_w(sb + SM_BUF0, 114688, 1024, tid); CPCOMMIT();
    run_layer<8, 16, 256>(sb + SM_BUF1, lane, Ahi, Alo, acc);
    epi_relu<16>(acc, bias + 384, q, Ahi, Alo);
    CPWAIT0(); __syncthreads();

    // L4: K=128, N=64, no ReLU; add b_out and store fp32
    run_layer<8, 8, 256>(sb + SM_BUF0, lane, Ahi, Alo, acc);
    {
        float* orow = out + ((size_t)blockIdx.x * 128 + wid * 16) * 64 + 2 * q;
#pragma unroll
        for (int nc = 0; nc < 8; ++nc) {
            float2 b = *(const float2*)(bias + 512 + nc * 8 + 2 * q);
            float2 v0 = make_float2(acc[nc][0] + b.x, acc[nc][1] + b.y);
            float2 v1 = make_float2(acc[nc][2] + b.x, acc[nc][3] + b.y);
            *(float2*)(orow + r0 * 64 + nc * 8)       = v0;
            *(float2*)(orow + (r0 + 8) * 64 + nc * 8) = v1;
        }
    }
}

extern "C" void kernel_launch(void* const* d_in, const int* in_sizes, int n_in,
                              void* d_out, int out_size) {
    const float* x     = (const float*)d_in[0];
    const float* w_in  = (const float*)d_in[1];
    const float* b_in  = (const float*)d_in[2];
    const float* w_hid = (const float*)d_in[3];
    const float* b_hid = (const float*)d_in[4];
    const float* w_out = (const float*)d_in[5];
    const float* b_out = (const float*)d_in[6];
    float* out = (float*)d_out;

    int n_rows = in_sizes[0] / 64;
    int grid = n_rows / 128;   // 8192

    cudaFuncSetAttribute(mlp_kernel, cudaFuncAttributeMaxDynamicSharedMemorySize,
                         SM_TOTAL);

    prep_weights<<<256, 256>>>(w_in, w_hid, w_out);
    mlp_kernel<<<grid, THREADS, SM_TOTAL>>>(x, b_in, b_hid, b_out, out);
}

// round 12
// speedup vs baseline: 2.4013x; 1.6689x over previous
#include <cuda_runtime.h>
#include <cuda_fp16.h>
#include <cstdint>

// ============================================================
// FullyFusedMLP 64 -> 128 -> 128 -> 128 -> 128 -> 64, ReLU on all but last.
// N = 1,048,576 rows fp32.  mma.sync.m16n8k16 pure fp16, fp32 accum
// (single pass; error budget ~6e-4 < 1e-3 gate).
// Activations stay in registers across all 5 layers.
// CTA = 128 threads / 64 rows -> 2 independent CTAs per SM so one CTA's
// mainloop hides the other's epilogue / weight-copy / barrier bubbles.
// ============================================================

#define THREADS 128

// Weight image (fp16), XOR-swizzled rows:
// l0: W_in [128,64]  rb=128B 16KB @ 0
// l1-3: W_hid[128,128] rb=256B 32KB @ 16384 / 49152 / 81920
// l4: W_out[64,128]  rb=256B 16KB @ 114688      total 128KB
__device__ __align__(256) unsigned char g_w[131072];

#define SM_BIAS 0           // 576 floats
#define SM_BUF0 4096        // 32KB weight buffer A
#define SM_BUF1 36864       // 32KB weight buffer B
#define SM_TOTAL 69632

static __device__ __forceinline__ uint32_t smem_u32(const void* p) {
    uint32_t a;
    asm("{ .reg .u64 t; cvta.to.shared.u64 t, %1; cvt.u32.u64 %0, t; }"
        : "=r"(a) : "l"(p));
    return a;
}

#define CP16(dst, src) \
    asm volatile("cp.async.cg.shared.global [%0], [%1], 16;\n" \
                 :: "r"(dst), "l"(src))
#define CPCOMMIT() asm volatile("cp.async.commit_group;\n" ::: "memory")
#define CPWAIT0()  asm volatile("cp.async.wait_group 0;\n" ::: "memory")

static __device__ __forceinline__ void ldsm_x4(uint32_t& r0, uint32_t& r1,
                                               uint32_t& r2, uint32_t& r3,
                                               uint32_t addr) {
    asm volatile("ldmatrix.sync.aligned.m8n8.x4.shared.b16 {%0,%1,%2,%3}, [%4];\n"
                 : "=r"(r0), "=r"(r1), "=r"(r2), "=r"(r3) : "r"(addr));
}

static __device__ __forceinline__ void mma16816(float acc[4], const uint32_t a[4],
                                                const uint32_t b[2]) {
    asm volatile(
        "mma.sync.aligned.m16n8k16.row.col.f32.f16.f16.f32 "
        "{%0,%1,%2,%3}, {%4,%5,%6,%7}, {%8,%9}, {%0,%1,%2,%3};\n"
        : "+f"(acc[0]), "+f"(acc[1]), "+f"(acc[2]), "+f"(acc[3])
        : "r"(a[0]), "r"(a[1]), "r"(a[2]), "r"(a[3]), "r"(b[0]), "r"(b[1]));
}

static __device__ __forceinline__ uint32_t packh2(float a, float b) {
    __half2 h = __floats2half2_rn(a, b);
    return *reinterpret_cast<uint32_t*>(&h);
}

// swizzled byte offset of W[n][k] within a weight block (rb = row bytes)
static __device__ __forceinline__ int wsw(int n, int k, int rb) {
    return n * rb + ((((k >> 3) ^ (n & 7))) << 4) + ((k & 7) << 1);
}

// ============================================================
// Prep: fp32 weights -> fp16 swizzled image
// ============================================================
__global__ void prep_weights(const float* __restrict__ w_in,
                             const float* __restrict__ w_hid,
                             const float* __restrict__ w_out) {
    int idx = blockIdx.x * blockDim.x + threadIdx.x;
    if (idx >= 65536) return;
    int l, n, k;
    float v;
    if (idx < 8192)       { l = 0; n = idx >> 6; k = idx & 63; v = w_in[idx]; }
    else if (idx < 57344) { int r = idx - 8192; l = 1 + (r >> 14);
                            n = (r >> 7) & 127; k = r & 127; v = w_hid[r]; }
    else                  { int r = idx - 57344; l = 4;
                            n = r >> 7; k = r & 127; v = w_out[r]; }
    const int woff[5] = {0, 16384, 49152, 81920, 114688};
    const int rb[5]   = {128, 256, 256, 256, 256};
    int off = woff[l] + wsw(n, k, rb[l]);
    *(__half*)(g_w + off) = __float2half_rn(v);
}

// ============================================================
// One layer: acc[NNC][4] = A * W^T.  4-column groups, j-major,
// double-buffered ldmatrix.x4 prefetch (one x4 = 2 n8-columns).
// Lane map: nl = lane&7 (row in 8-group), h8 = (lane>>3)&1 (k-half),
// cp = lane>>4 (column of pair).
// ============================================================
template <int NKC, int NNC, int RB>
static __device__ __forceinline__ void run_layer(uint32_t wsm, int lane,
                                                 const uint32_t A[8][4],
                                                 float acc[16][4]) {
    const int nl = lane & 7;
    const int h8 = (lane >> 3) & 1;
    const int cp = lane >> 4;
#pragma unroll
    for (int g = 0; g < NNC / 4; ++g) {
#pragma unroll
        for (int c = 0; c < 4; ++c)
#pragma unroll
            for (int r = 0; r < 4; ++r) acc[4 * g + c][r] = 0.f;

        uint32_t B[2][8];   // [buffer][2 col-pairs x 2 cols x 2 regs]
        const uint32_t base = wsm + (uint32_t)((32 * g + 8 * cp + nl) * RB);
        {
            uint32_t sw = (uint32_t)((h8 ^ nl) << 4);
            ldsm_x4(B[0][0], B[0][1], B[0][2], B[0][3], base + sw);
            ldsm_x4(B[0][4], B[0][5], B[0][6], B[0][7], base + 16 * RB + sw);
        }
#pragma unroll
        for (int j = 0; j < NKC; ++j) {
            const int cb = j & 1, nb = cb ^ 1;
            if (j + 1 < NKC) {
                uint32_t sw = (uint32_t)(((2 * (j + 1) + h8) ^ nl) << 4);
                ldsm_x4(B[nb][0], B[nb][1], B[nb][2], B[nb][3], base + sw);
                ldsm_x4(B[nb][4], B[nb][5], B[nb][6], B[nb][7], base + 16 * RB + sw);
            }
            mma16816(acc[4 * g + 0], A[j], &B[cb][0]);
            mma16816(acc[4 * g + 1], A[j], &B[cb][2]);
            mma16816(acc[4 * g + 2], A[j], &B[cb][4]);
            mma16816(acc[4 * g + 3], A[j], &B[cb][6]);
        }
    }
}

// bias + ReLU + fp16 pack; C-frag pairs become next-layer A-frags in place.
template <int NNC>
static __device__ __forceinline__ void epi_relu(const float acc[16][4], const float* bsm,
                                                int q, uint32_t A[8][4]) {
#pragma unroll
    for (int tc = 0; tc < NNC / 2; ++tc) {
#pragma unroll
        for (int h = 0; h < 2; ++h) {
            const float* a = acc[2 * tc + h];
            float2 b = *(const float2*)(bsm + (2 * tc + h) * 8 + 2 * q);
            float v0 = fmaxf(a[0] + b.x, 0.f), v1 = fmaxf(a[1] + b.y, 0.f);
            float v2 = fmaxf(a[2] + b.x, 0.f), v3 = fmaxf(a[3] + b.y, 0.f);
            A[tc][2 * h + 0] = packh2(v0, v1);
            A[tc][2 * h + 1] = packh2(v2, v3);
        }
    }
}

static __device__ __forceinline__ void copy_w(uint32_t dst, int gofs, int n16, int tid) {
    unsigned long long src =
        (unsigned long long)__cvta_generic_to_global(g_w + gofs);
    for (int i = tid; i < n16; i += THREADS)
        CP16(dst + (uint32_t)(i * 16), src + (unsigned long long)i * 16);
}

// ============================================================
// Main kernel: 1 CTA = 64 rows, 4 warps x 16 rows, 2 CTAs/SM.
// ============================================================
__global__ void __launch_bounds__(THREADS, 2)
mlp_kernel(const float* __restrict__ x, const float* __restrict__ b_in,
           const float* __restrict__ b_hid, const float* __restrict__ b_out,
           float* __restrict__ out) {
    extern __shared__ char smem[];
    const uint32_t sb = smem_u32(smem);
    const int tid = threadIdx.x, wid = tid >> 5, lane = tid & 31;
    const int q = lane & 3, r0 = lane >> 2;
    float* bias = (float*)(smem + SM_BIAS);

    if (tid < 128) bias[tid] = b_in[tid];
    for (int i = tid; i < 384; i += THREADS) bias[128 + i] = b_hid[i];
    if (tid < 64) bias[512 + tid] = b_out[tid];

    // start layer-0 weight copy (16KB) immediately
    copy_w(sb + SM_BUF0, 0, 1024, tid);
    CPCOMMIT();

    // ---- load input tile as fp16 A-fragments (K=64 -> 4 chunks) ----
    uint32_t A[8][4];
    {
        const float* xr = x + ((size_t)blockIdx.x * 64 + wid * 16) * 64 + 2 * q;
#pragma unroll
        for (int j = 0; j < 4; ++j)
#pragma unroll
            for (int p = 0; p < 4; ++p) {
                int dr = (p & 1) * 8, dk = (p >> 1) * 8;
                float2 v = *(const float2*)(xr + (r0 + dr) * 64 + j * 16 + dk);
                A[j][p] = packh2(v.x, v.y);
            }
    }
    CPWAIT0();
    __syncthreads();

    float acc[16][4];

    // L0: K=64, N=128, weights in BUF0; prefetch L1 into BUF1
    copy_w(sb + SM_BUF1, 16384, 2048, tid); CPCOMMIT();
    run_layer<4, 16, 128>(sb + SM_BUF0, lane, A, acc);
    epi_relu<16>(acc, bias + 0, q, A);
    CPWAIT0(); __syncthreads();

    // L1: BUF1; prefetch L2 into BUF0
    copy_w(sb + SM_BUF0, 49152, 2048, tid); CPCOMMIT();
    run_layer<8, 16, 256>(sb + SM_BUF1, lane, A, acc);
    epi_relu<16>(acc, bias + 128, q, A);
    CPWAIT0(); __syncthreads();

    // L2: BUF0; prefetch L3 into BUF1
    copy_w(sb + SM_BUF1, 81920, 2048, tid); CPCOMMIT();
    run_layer<8, 16, 256>(sb + SM_BUF0, lane, A, acc);
    epi_relu<16>(acc, bias + 256, q, A);
    CPWAIT0(); __syncthreads();

    // L3: BUF1; prefetch L4 (16KB) into BUF0
    copy_w(sb + SM_BUF0, 114688, 1024, tid); CPCOMMIT();
    run_layer<8, 16, 256>(sb + SM_BUF1, lane, A, acc);
    epi_relu<16>(acc, bias + 384, q, A);
    CPWAIT0(); __syncthreads();

    // L4: K=128, N=64, no ReLU; add b_out and store fp32
    run_layer<8, 8, 256>(sb + SM_BUF0, lane, A, acc);
    {
        float* orow = out + ((size_t)blockIdx.x * 64 + wid * 16) * 64 + 2 * q;
#pragma unroll
        for (int nc = 0; nc < 8; ++nc) {
            float2 b = *(const float2*)(bias + 512 + nc * 8 + 2 * q);
            float2 v0 = make_float2(acc[nc][0] + b.x, acc[nc][1] + b.y);
            float2 v1 = make_float2(acc[nc][2] + b.x, acc[nc][3] + b.y);
            *(float2*)(orow + r0 * 64 + nc * 8)       = v0;
            *(float2*)(orow + (r0 + 8) * 64 + nc * 8) = v1;
        }
    }
}

extern "C" void kernel_launch(void* const* d_in, const int* in_sizes, int n_in,
                              void* d_out, int out_size) {
    const float* x     = (const float*)d_in[0];
    const float* w_in  = (const float*)d_in[1];
    const float* b_in  = (const float*)d_in[2];
    const float* w_hid = (const float*)d_in[3];
    const float* b_hid = (const float*)d_in[4];
    const float* w_out = (const float*)d_in[5];
    const float* b_out = (const float*)d_in[6];
    float* out = (float*)d_out;

    int n_rows = in_sizes[0] / 64;
    int grid = n_rows / 64;   // 16384

    cudaFuncSetAttribute(mlp_kernel, cudaFuncAttributeMaxDynamicSharedMemorySize,
                         SM_TOTAL);

    prep_weights<<<256, 256>>>(w_in, w_hid, w_out);
    mlp_kernel<<<grid, THREADS, SM_TOTAL>>>(x, b_in, b_hid, b_out, out);
}

// round 13
// speedup vs baseline: 2.8754x; 1.1974x over previous
#include <cuda_runtime.h>
#include <cuda_fp16.h>
#include <cstdint>

// ============================================================
// FullyFusedMLP 64 -> 128 -> 128 -> 128 -> 128 -> 64, ReLU on all but last.
// N = 1,048,576 rows fp32.  mma.sync.m16n8k16 pure fp16, fp32 accum.
// Activations stay in registers across all 5 layers (ping-pong A buffers).
// Warp = 32 rows (2 rowgroups): each B fragment pair feeds 8 MMAs, halving
// ldmatrix traffic per row vs 16-row warps. N processed in 32-col chunks.
// CTA = 128 threads / 128 rows, 2 CTAs/SM.
// ============================================================

#define THREADS 128

// Weight image (fp16), XOR-swizzled rows:
// l0: W_in [128,64]  rb=128B 16KB @ 0
// l1-3: W_hid[128,128] rb=256B 32KB @ 16384 / 49152 / 81920
// l4: W_out[64,128]  rb=256B 16KB @ 114688      total 128KB
__device__ __align__(256) unsigned char g_w[131072];

#define SM_BIAS 0           // 576 floats
#define SM_BUF0 4096        // 32KB weight buffer A
#define SM_BUF1 36864       // 32KB weight buffer B
#define SM_TOTAL 69632

static __device__ __forceinline__ uint32_t smem_u32(const void* p) {
    uint32_t a;
    asm("{ .reg .u64 t; cvta.to.shared.u64 t, %1; cvt.u32.u64 %0, t; }"
        : "=r"(a) : "l"(p));
    return a;
}

#define CP16(dst, src) \
    asm volatile("cp.async.cg.shared.global [%0], [%1], 16;\n" \
                 :: "r"(dst), "l"(src))
#define CPCOMMIT() asm volatile("cp.async.commit_group;\n" ::: "memory")
#define CPWAIT0()  asm volatile("cp.async.wait_group 0;\n" ::: "memory")

static __device__ __forceinline__ void ldsm_x4(uint32_t& r0, uint32_t& r1,
                                               uint32_t& r2, uint32_t& r3,
                                               uint32_t addr) {
    asm volatile("ldmatrix.sync.aligned.m8n8.x4.shared.b16 {%0,%1,%2,%3}, [%4];\n"
                 : "=r"(r0), "=r"(r1), "=r"(r2), "=r"(r3) : "r"(addr));
}

static __device__ __forceinline__ void mma16816(float acc[4], const uint32_t a[4],
                                                const uint32_t b[2]) {
    asm volatile(
        "mma.sync.aligned.m16n8k16.row.col.f32.f16.f16.f32 "
        "{%0,%1,%2,%3}, {%4,%5,%6,%7}, {%8,%9}, {%0,%1,%2,%3};\n"
        : "+f"(acc[0]), "+f"(acc[1]), "+f"(acc[2]), "+f"(acc[3])
        : "r"(a[0]), "r"(a[1]), "r"(a[2]), "r"(a[3]), "r"(b[0]), "r"(b[1]));
}

static __device__ __forceinline__ uint32_t packh2(float a, float b) {
    __half2 h = __floats2half2_rn(a, b);
    return *reinterpret_cast<uint32_t*>(&h);
}

// swizzled byte offset of W[n][k] within a weight block (rb = row bytes)
static __device__ __forceinline__ int wsw(int n, int k, int rb) {
    return n * rb + ((((k >> 3) ^ (n & 7))) << 4) + ((k & 7) << 1);
}

// ============================================================
// Prep: fp32 weights -> fp16 swizzled image
// ============================================================
__global__ void prep_weights(const float* __restrict__ w_in,
                             const float* __restrict__ w_hid,
                             const float* __restrict__ w_out) {
    int idx = blockIdx.x * blockDim.x + threadIdx.x;
    if (idx >= 65536) return;
    int l, n, k;
    float v;
    if (idx < 8192)       { l = 0; n = idx >> 6; k = idx & 63; v = w_in[idx]; }
    else if (idx < 57344) { int r = idx - 8192; l = 1 + (r >> 14);
                            n = (r >> 7) & 127; k = r & 127; v = w_hid[r]; }
    else                  { int r = idx - 57344; l = 4;
                            n = r >> 7; k = r & 127; v = w_out[r]; }
    const int woff[5] = {0, 16384, 49152, 81920, 114688};
    const int rb[5]   = {128, 256, 256, 256, 256};
    int off = woff[l] + wsw(n, k, rb[l]);
    *(__half*)(g_w + off) = __float2half_rn(v);
}

// ============================================================
// Fused layer: Aout = relu(Ain * W^T + b)  (RELU=0 on last layer).
// Warp covers 32 rows (2 rowgroups). N in 32-col chunks; per k-step a
// 2x ldmatrix.x4 B pair (double-buffered) feeds 8 MMAs.
// Lane map: nl = lane&7, h8 = (lane>>3)&1 (k-half), cp = lane>>4.
// ============================================================
template <int NKC, int NNC, int RB, int RELU>
static __device__ __forceinline__ void layer_fused(uint32_t wsm, int lane, int q,
                                                   const uint32_t Ain[2][8][4],
                                                   uint32_t Aout[2][8][4],
                                                   const float* bsm) {
    const int nl = lane & 7;
    const int h8 = (lane >> 3) & 1;
    const int cp = lane >> 4;
#pragma unroll
    for (int nc = 0; nc < NNC / 4; ++nc) {      // 32-column chunk
        float acc[2][4][4];
#pragma unroll
        for (int r = 0; r < 2; ++r)
#pragma unroll
            for (int c = 0; c < 4; ++c)
#pragma unroll
                for (int e = 0; e < 4; ++e) acc[r][c][e] = 0.f;

        uint32_t B[2][8];
        const uint32_t base = wsm + (uint32_t)((32 * nc + 8 * cp + nl) * RB);
        {
            uint32_t sw = (uint32_t)((h8 ^ nl) << 4);
            ldsm_x4(B[0][0], B[0][1], B[0][2], B[0][3], base + sw);
            ldsm_x4(B[0][4], B[0][5], B[0][6], B[0][7], base + 16 * RB + sw);
        }
#pragma unroll
        for (int j = 0; j < NKC; ++j) {
            const int cb = j & 1, nb = cb ^ 1;
            if (j + 1 < NKC) {
                uint32_t sw = (uint32_t)(((2 * (j + 1) + h8) ^ nl) << 4);
                ldsm_x4(B[nb][0], B[nb][1], B[nb][2], B[nb][3], base + sw);
                ldsm_x4(B[nb][4], B[nb][5], B[nb][6], B[nb][7], base + 16 * RB + sw);
            }
#pragma unroll
            for (int r = 0; r < 2; ++r) {
                mma16816(acc[r][0], Ain[r][j], &B[cb][0]);
                mma16816(acc[r][1], Ain[r][j], &B[cb][2]);
                mma16816(acc[r][2], Ain[r][j], &B[cb][4]);
                mma16816(acc[r][3], Ain[r][j], &B[cb][6]);
            }
        }
        // epilogue for this 32-col chunk -> next-layer A k-chunks 2nc, 2nc+1
#pragma unroll
        for (int r = 0; r < 2; ++r)
#pragma unroll
            for (int c = 0; c < 4; ++c) {
                const float* a = acc[r][c];
                float2 b = *(const float2*)(bsm + 32 * nc + 8 * c + 2 * q);
                float v0 = a[0] + b.x, v1 = a[1] + b.y;
                float v2 = a[2] + b.x, v3 = a[3] + b.y;
                if (RELU) {
                    v0 = fmaxf(v0, 0.f); v1 = fmaxf(v1, 0.f);
                    v2 = fmaxf(v2, 0.f); v3 = fmaxf(v3, 0.f);
                }
                Aout[r][2 * nc + (c >> 1)][2 * (c & 1) + 0] = packh2(v0, v1);
                Aout[r][2 * nc + (c >> 1)][2 * (c & 1) + 1] = packh2(v2, v3);
            }
    }
}

static __device__ __forceinline__ void copy_w(uint32_t dst, int gofs, int n16, int tid) {
    unsigned long long src =
        (unsigned long long)__cvta_generic_to_global(g_w + gofs);
    for (int i = tid; i < n16; i += THREADS)
        CP16(dst + (uint32_t)(i * 16), src + (unsigned long long)i * 16);
}

// ============================================================
// Main kernel: 1 CTA = 128 rows, 4 warps x 32 rows, 2 CTAs/SM.
// ============================================================
__global__ void __launch_bounds__(THREADS, 2)
mlp_kernel(const float* __restrict__ x, const float* __restrict__ b_in,
           const float* __restrict__ b_hid, const float* __restrict__ b_out,
           float* __restrict__ out) {
    extern __shared__ char smem[];
    const uint32_t sb = smem_u32(smem);
    const int tid = threadIdx.x, wid = tid >> 5, lane = tid & 31;
    const int q = lane & 3, r0 = lane >> 2;
    float* bias = (float*)(smem + SM_BIAS);

    if (tid < 128) bias[tid] = b_in[tid];
    for (int i = tid; i < 384; i += THREADS) bias[128 + i] = b_hid[i];
    if (tid < 64) bias[512 + tid] = b_out[tid];

    // start layer-0 weight copy (16KB) immediately
    copy_w(sb + SM_BUF0, 0, 1024, tid);
    CPCOMMIT();

    // ---- load input: 32 rows/warp as fp16 A-fragments (K=64 -> 4 chunks) ----
    uint32_t A0[2][8][4], A1[2][8][4];
    {
#pragma unroll
        for (int r = 0; r < 2; ++r) {
            const float* xr = x + ((size_t)blockIdx.x * 128 + wid * 32 + r * 16) * 64 + 2 * q;
#pragma unroll
            for (int j = 0; j < 4; ++j)
#pragma unroll
                for (int p = 0; p < 4; ++p) {
                    int dr = (p & 1) * 8, dk = (p >> 1) * 8;
                    float2 v = *(const float2*)(xr + (r0 + dr) * 64 + j * 16 + dk);
                    A0[r][j][p] = packh2(v.x, v.y);
                }
        }
    }
    CPWAIT0();
    __syncthreads();

    // L0: K=64, N=128, BUF0; prefetch L1 into BUF1
    copy_w(sb + SM_BUF1, 16384, 2048, tid); CPCOMMIT();
    layer_fused<4, 16, 128, 1>(sb + SM_BUF0, lane, q, A0, A1, bias + 0);
    CPWAIT0(); __syncthreads();

    // L1: BUF1; prefetch L2 into BUF0
    copy_w(sb + SM_BUF0, 49152, 2048, tid); CPCOMMIT();
    layer_fused<8, 16, 256, 1>(sb + SM_BUF1, lane, q, A1, A0, bias + 128);
    CPWAIT0(); __syncthreads();

    // L2: BUF0; prefetch L3 into BUF1
    copy_w(sb + SM_BUF1, 81920, 2048, tid); CPCOMMIT();
    layer_fused<8, 16, 256, 1>(sb + SM_BUF0, lane, q, A0, A1, bias + 256);
    CPWAIT0(); __syncthreads();

    // L3: BUF1; prefetch L4 (16KB) into BUF0
    copy_w(sb + SM_BUF0, 114688, 1024, tid); CPCOMMIT();
    layer_fused<8, 16, 256, 1>(sb + SM_BUF1, lane, q, A1, A0, bias + 384);
    CPWAIT0(); __syncthreads();

    // L4: K=128, N=64, no ReLU -> A1 holds packed fp16 outputs; unpack+store
    layer_fused<8, 8, 256, 0>(sb + SM_BUF0, lane, q, A0, A1, bias + 512);
    {
#pragma unroll
        for (int r = 0; r < 2; ++r) {
            float* orow = out + ((size_t)blockIdx.x * 128 + wid * 32 + r * 16) * 64 + 2 * q;
#pragma unroll
            for (int j = 0; j < 4; ++j)      // 4 k-chunks cover 64 cols
#pragma unroll
                for (int p = 0; p < 4; ++p) {
                    int dr = (p & 1) * 8, dk = (p >> 1) * 8;
                    __half2 h = *reinterpret_cast<__half2*>(&A1[r][j][p]);
                    float2 v = __half22float2(h);
                    *(float2*)(orow + (r0 + dr) * 64 + j * 16 + dk) = v;
                }
        }
    }
}

extern "C" void kernel_launch(void* const* d_in, const int* in_sizes, int n_in,
                              void* d_out, int out_size) {
    const float* x     = (const float*)d_in[0];
    const float* w_in  = (const float*)d_in[1];
    const float* b_in  = (const float*)d_in[2];
    const float* w_hid = (const float*)d_in[3];
    const float* b_hid = (const float*)d_in[4];
    const float* w_out = (const float*)d_in[5];
    const float* b_out = (const float*)d_in[6];
    float* out = (float*)d_out;

    int n_rows = in_sizes[0] / 64;
    int grid = n_rows / 128;   // 8192

    cudaFuncSetAttribute(mlp_kernel, cudaFuncAttributeMaxDynamicSharedMemorySize,
                         SM_TOTAL);

    prep_weights<<<256, 256>>>(w_in, w_hid, w_out);
    mlp_kernel<<<grid, THREADS, SM_TOTAL>>>(x, b_in, b_hid, b_out, out);
}

// round 14
// speedup vs baseline: 3.0791x; 1.0708x over previous
#include <cuda_runtime.h>
#include <cuda_fp16.h>
#include <cstdint>

// ============================================================
// FullyFusedMLP 64 -> 128 -> 128 -> 128 -> 128 -> 64, ReLU on all but last.
// N = 1,048,576 rows fp32.  mma.sync.m16n8k16 pure fp16, fp32 accum.
// PERSISTENT version: 148 CTAs (1/SM, 256 threads). All weights loaded to
// SMEM once; each warp then grid-strides over 32-row chunks with ZERO
// in-loop synchronization (no barriers, no weight copies).
// ============================================================

#define THREADS 256

// Weight image (fp16), XOR-swizzled rows:
// l0: W_in [128,64]  rb=128B 16KB @ 0
// l1-3: W_hid[128,128] rb=256B 32KB @ 16384 / 49152 / 81920
// l4: W_out[64,128]  rb=256B 16KB @ 114688      total 128KB
__device__ __align__(256) unsigned char g_w[131072];

#define SM_BIAS 0            // 576 floats
#define SM_W    4096         // 128KB weight image
#define SM_TOTAL 135168

static __device__ __forceinline__ uint32_t smem_u32(const void* p) {
    uint32_t a;
    asm("{ .reg .u64 t; cvta.to.shared.u64 t, %1; cvt.u32.u64 %0, t; }"
        : "=r"(a) : "l"(p));
    return a;
}

#define CP16(dst, src) \
    asm volatile("cp.async.cg.shared.global [%0], [%1], 16;\n" \
                 :: "r"(dst), "l"(src))
#define CPCOMMIT() asm volatile("cp.async.commit_group;\n" ::: "memory")
#define CPWAIT0()  asm volatile("cp.async.wait_group 0;\n" ::: "memory")

static __device__ __forceinline__ void ldsm_x4(uint32_t& r0, uint32_t& r1,
                                               uint32_t& r2, uint32_t& r3,
                                               uint32_t addr) {
    asm volatile("ldmatrix.sync.aligned.m8n8.x4.shared.b16 {%0,%1,%2,%3}, [%4];\n"
                 : "=r"(r0), "=r"(r1), "=r"(r2), "=r"(r3) : "r"(addr));
}

static __device__ __forceinline__ void mma16816(float acc[4], const uint32_t a[4],
                                                const uint32_t b[2]) {
    asm volatile(
        "mma.sync.aligned.m16n8k16.row.col.f32.f16.f16.f32 "
        "{%0,%1,%2,%3}, {%4,%5,%6,%7}, {%8,%9}, {%0,%1,%2,%3};\n"
        : "+f"(acc[0]), "+f"(acc[1]), "+f"(acc[2]), "+f"(acc[3])
        : "r"(a[0]), "r"(a[1]), "r"(a[2]), "r"(a[3]), "r"(b[0]), "r"(b[1]));
}

static __device__ __forceinline__ uint32_t packh2(float a, float b) {
    __half2 h = __floats2half2_rn(a, b);
    return *reinterpret_cast<uint32_t*>(&h);
}

// swizzled byte offset of W[n][k] within a weight block (rb = row bytes)
static __device__ __forceinline__ int wsw(int n, int k, int rb) {
    return n * rb + ((((k >> 3) ^ (n & 7))) << 4) + ((k & 7) << 1);
}

// ============================================================
// Prep: fp32 weights -> fp16 swizzled image
// ============================================================
__global__ void prep_weights(const float* __restrict__ w_in,
                             const float* __restrict__ w_hid,
                             const float* __restrict__ w_out) {
    int idx = blockIdx.x * blockDim.x + threadIdx.x;
    if (idx >= 65536) return;
    int l, n, k;
    float v;
    if (idx < 8192)       { l = 0; n = idx >> 6; k = idx & 63; v = w_in[idx]; }
    else if (idx < 57344) { int r = idx - 8192; l = 1 + (r >> 14);
                            n = (r >> 7) & 127; k = r & 127; v = w_hid[r]; }
    else                  { int r = idx - 57344; l = 4;
                            n = r >> 7; k = r & 127; v = w_out[r]; }
    const int woff[5] = {0, 16384, 49152, 81920, 114688};
    const int rb[5]   = {128, 256, 256, 256, 256};
    int off = woff[l] + wsw(n, k, rb[l]);
    *(__half*)(g_w + off) = __float2half_rn(v);
}

// ============================================================
// Fused layer: Aout = relu(Ain * W^T + b)  (RELU=0 on last layer).
// Warp covers 32 rows (2 rowgroups). N in 32-col chunks; per k-step a
// 2x ldmatrix.x4 B pair (double-buffered) feeds 8 MMAs.
// Lane map: nl = lane&7, h8 = (lane>>3)&1 (k-half), cp = lane>>4.
// ============================================================
template <int NKC, int NNC, int RB, int RELU>
static __device__ __forceinline__ void layer_fused(uint32_t wsm, int lane, int q,
                                                   const uint32_t Ain[2][8][4],
                                                   uint32_t Aout[2][8][4],
                                                   const float* bsm) {
    const int nl = lane & 7;
    const int h8 = (lane >> 3) & 1;
    const int cp = lane >> 4;
#pragma unroll
    for (int nc = 0; nc < NNC / 4; ++nc) {      // 32-column chunk
        float acc[2][4][4];
#pragma unroll
        for (int r = 0; r < 2; ++r)
#pragma unroll
            for (int c = 0; c < 4; ++c)
#pragma unroll
                for (int e = 0; e < 4; ++e) acc[r][c][e] = 0.f;

        uint32_t B[2][8];
        const uint32_t base = wsm + (uint32_t)((32 * nc + 8 * cp + nl) * RB);
        {
            uint32_t sw = (uint32_t)((h8 ^ nl) << 4);
            ldsm_x4(B[0][0], B[0][1], B[0][2], B[0][3], base + sw);
            ldsm_x4(B[0][4], B[0][5], B[0][6], B[0][7], base + 16 * RB + sw);
        }
#pragma unroll
        for (int j = 0; j < NKC; ++j) {
            const int cb = j & 1, nb = cb ^ 1;
            if (j + 1 < NKC) {
                uint32_t sw = (uint32_t)(((2 * (j + 1) + h8) ^ nl) << 4);
                ldsm_x4(B[nb][0], B[nb][1], B[nb][2], B[nb][3], base + sw);
                ldsm_x4(B[nb][4], B[nb][5], B[nb][6], B[nb][7], base + 16 * RB + sw);
            }
#pragma unroll
            for (int r = 0; r < 2; ++r) {
                mma16816(acc[r][0], Ain[r][j], &B[cb][0]);
                mma16816(acc[r][1], Ain[r][j], &B[cb][2]);
                mma16816(acc[r][2], Ain[r][j], &B[cb][4]);
                mma16816(acc[r][3], Ain[r][j], &B[cb][6]);
            }
        }
        // epilogue for this 32-col chunk -> next-layer A k-chunks 2nc, 2nc+1
#pragma unroll
        for (int r = 0; r < 2; ++r)
#pragma unroll
            for (int c = 0; c < 4; ++c) {
                const float* a = acc[r][c];
                float2 b = *(const float2*)(bsm + 32 * nc + 8 * c + 2 * q);
                float v0 = a[0] + b.x, v1 = a[1] + b.y;
                float v2 = a[2] + b.x, v3 = a[3] + b.y;
                if (RELU) {
                    v0 = fmaxf(v0, 0.f); v1 = fmaxf(v1, 0.f);
                    v2 = fmaxf(v2, 0.f); v3 = fmaxf(v3, 0.f);
                }
                Aout[r][2 * nc + (c >> 1)][2 * (c & 1) + 0] = packh2(v0, v1);
                Aout[r][2 * nc + (c >> 1)][2 * (c & 1) + 1] = packh2(v2, v3);
            }
    }
}

// ============================================================
// Main persistent kernel: 148 CTAs x 256 threads. Weights resident in
// SMEM; each warp grid-strides over 32-row chunks, no in-loop sync.
// ============================================================
__global__ void __launch_bounds__(THREADS, 1)
mlp_kernel(const float* __restrict__ x, const float* __restrict__ b_in,
           const float* __restrict__ b_hid, const float* __restrict__ b_out,
           float* __restrict__ out, int nchunks) {
    extern __shared__ char smem[];
    const uint32_t sb = smem_u32(smem);
    const int tid = threadIdx.x, wid = tid >> 5, lane = tid & 31;
    const int q = lane & 3, r0 = lane >> 2;
    float* bias = (float*)(smem + SM_BIAS);

    // ---- one-time: biases + full weight image -> SMEM ----
    if (tid < 128) bias[tid] = b_in[tid];
    for (int i = tid; i < 384; i += THREADS) bias[128 + i] = b_hid[i];
    if (tid < 64) bias[512 + tid] = b_out[tid];
    {
        unsigned long long src = (unsigned long long)__cvta_generic_to_global(g_w);
        for (int i = tid; i < 8192; i += THREADS)
            CP16(sb + SM_W + (uint32_t)(i * 16), src + (unsigned long long)i * 16);
    }
    CPCOMMIT();
    CPWAIT0();
    __syncthreads();

    const uint32_t ws = sb + SM_W;
    const int stride = (int)gridDim.x * (THREADS / 32);
    uint32_t A0[2][8][4], A1[2][8][4];

    for (int c = blockIdx.x * (THREADS / 32) + wid; c < nchunks; c += stride) {
        // ---- load 32-row input chunk as fp16 A-fragments (K=64 -> 4 chunks) ----
#pragma unroll
        for (int r = 0; r < 2; ++r) {
            const float* xr = x + ((size_t)c * 32 + r * 16) * 64 + 2 * q;
#pragma unroll
            for (int j = 0; j < 4; ++j)
#pragma unroll
                for (int p = 0; p < 4; ++p) {
                    int dr = (p & 1) * 8, dk = (p >> 1) * 8;
                    float2 v = *(const float2*)(xr + (r0 + dr) * 64 + j * 16 + dk);
                    A0[r][j][p] = packh2(v.x, v.y);
                }
        }

        layer_fused<4, 16, 128, 1>(ws + 0,      lane, q, A0, A1, bias + 0);
        layer_fused<8, 16, 256, 1>(ws + 16384,  lane, q, A1, A0, bias + 128);
        layer_fused<8, 16, 256, 1>(ws + 49152,  lane, q, A0, A1, bias + 256);
        layer_fused<8, 16, 256, 1>(ws + 81920,  lane, q, A1, A0, bias + 384);
        layer_fused<8, 8, 256, 0>(ws + 114688,  lane, q, A0, A1, bias + 512);

        // ---- store 32-row output chunk (unpack fp16 -> fp32) ----
#pragma unroll
        for (int r = 0; r < 2; ++r) {
            float* orow = out + ((size_t)c * 32 + r * 16) * 64 + 2 * q;
#pragma unroll
            for (int j = 0; j < 4; ++j)      // 4 k-chunks cover 64 cols
#pragma unroll
                for (int p = 0; p < 4; ++p) {
                    int dr = (p & 1) * 8, dk = (p >> 1) * 8;
                    __half2 h = *reinterpret_cast<__half2*>(&A1[r][j][p]);
                    float2 v = __half22float2(h);
                    *(float2*)(orow + (r0 + dr) * 64 + j * 16 + dk) = v;
                }
        }
    }
}

extern "C" void kernel_launch(void* const* d_in, const int* in_sizes, int n_in,
                              void* d_out, int out_size) {
    const float* x     = (const float*)d_in[0];
    const float* w_in  = (const float*)d_in[1];
    const float* b_in  = (const float*)d_in[2];
    const float* w_hid = (const float*)d_in[3];
    const float* b_hid = (const float*)d_in[4];
    const float* w_out = (const float*)d_in[5];
    const float* b_out = (const float*)d_in[6];
    float* out = (float*)d_out;

    int n_rows = in_sizes[0] / 64;
    int nchunks = n_rows / 32;          // 32768

    cudaFuncSetAttribute(mlp_kernel, cudaFuncAttributeMaxDynamicSharedMemorySize,
                         SM_TOTAL);

    prep_weights<<<256, 256>>>(w_in, w_hid, w_out);
    mlp_kernel<<<148, THREADS, SM_TOTAL>>>(x, b_in, b_hid, b_out, out, nchunks);
}